// round 13
// baseline (speedup 1.0000x reference)
#include <cuda_runtime.h>
#include <cstdint>

#define NT  64          // threads per CTA
#define NPB 128         // problems per CTA: thread t packs problems (base+2t, base+2t+1)
#define SMS 130         // floats per slot: even -> (s*130 + 2t)*4 is 8B-aligned; banks (2s+2t)%32 conflict-free

typedef unsigned long long f2;   // packed (lo,hi) fp32 pair

__device__ __forceinline__ f2 pk2(float lo, float hi) {
    f2 r; asm("mov.b64 %0,{%1,%2};" : "=l"(r) : "f"(lo), "f"(hi)); return r;
}
__device__ __forceinline__ void upk2(f2 x, float& lo, float& hi) {
    asm("mov.b64 {%0,%1},%2;" : "=f"(lo), "=f"(hi) : "l"(x));
}
__device__ __forceinline__ f2 fma2(f2 a, f2 b, f2 c) {
    f2 d; asm("fma.rn.f32x2 %0,%1,%2,%3;" : "=l"(d) : "l"(a), "l"(b), "l"(c)); return d;
}
__device__ __forceinline__ f2 mul2(f2 a, f2 b) {
    f2 d; asm("mul.rn.f32x2 %0,%1,%2;" : "=l"(d) : "l"(a), "l"(b)); return d;
}
__device__ __forceinline__ f2 add2(f2 a, f2 b) {
    f2 d; asm("add.rn.f32x2 %0,%1,%2;" : "=l"(d) : "l"(a), "l"(b)); return d;
}
__device__ __forceinline__ f2 neg2(f2 a) { return a ^ 0x8000000080000000ULL; }

// packed symmetric index for 13x13 (upper triangle), compile-time after unroll
__device__ __forceinline__ int sidx(int r, int c) {
    int lo = r < c ? r : c;
    int hi = r < c ? c : r;
    return lo * 13 - (lo * (lo - 1)) / 2 + (hi - lo);
}
// upper-tri 6x6 flat index
__device__ __forceinline__ int tidx6(int i, int j) {
    return i * 6 - (i * (i - 1)) / 2 + (j - i);
}

__device__ __forceinline__ void expm_coefs(float th2, float& sA, float& sB, float& sC) {
    if (th2 > 1e-2f) {
        const float th = sqrtf(th2);
        float sn, cn;
        __sincosf(th, &sn, &cn);
        sA = sn / th;
        sB = (1.0f - cn) / th2;
        sC = (1.0f - sA) / th2;
    } else {
        sA = 1.0f - th2 * (1.0f/6.0f)  + th2*th2 * (1.0f/120.0f);
        sB = 0.5f - th2 * (1.0f/24.0f) + th2*th2 * (1.0f/720.0f);
        sC = (1.0f/6.0f) - th2 * (1.0f/120.0f) + th2*th2 * (1.0f/5040.0f);
    }
}

// accumulate coeff*w[j] into packed upper-tri Q (I literal)
#define ACC2(I, CF) do { const f2 cf_ = (CF); _Pragma("unroll") \
    for (int j = (I); j < 7; j++) Q2[(I)][j] = fma2(cf_, w[j], Q2[(I)][j]); } while (0)

__global__ void __launch_bounds__(NT, 4)
mtm_refine_kernel(const float* __restrict__ Min, const float* __restrict__ Tin,
                  float* __restrict__ outT, float* __restrict__ outOm, int N)
{
    __shared__ __align__(16) float smf[91 * SMS];   // 47,320 B
    __shared__ unsigned short lut[169];             // element -> slot * SMS

    const int tid  = threadIdx.x;
    const int base = blockIdx.x * NPB;

    // ---- element->packed-slot LUT ----
    for (int e = tid; e < 169; e += NT) {
        const int r = e / 13, c = e - (e / 13) * 13;
        const int lo = r < c ? r : c;
        const int hi = r < c ? c : r;
        lut[e] = (unsigned short)((lo * 13 - ((lo * (lo - 1)) >> 1) + (hi - lo)) * SMS);
    }
    __syncthreads();

    // ---- R5-proven vectorized cooperative fill (float4 LDG + LUT STS) ----
    {
        int np = N - base; if (np > NPB) np = NPB;
        const int limit  = np * 169;
        const int limit4 = limit >> 2;
        const float4* g4 = (const float4*)(Min + (size_t)base * 169);

        int p = 0, e = 4 * tid;
        if (e >= 169) { e -= 169; p++; }     // 4*tid <= 252 < 338
        for (int i4 = tid; i4 < limit4; i4 += NT) {
            const float4 v = g4[i4];
            int ek = e, pk = p;
            if (ek >= 169) { ek -= 169; pk++; } smf[(int)lut[ek] + pk] = v.x; ek++;
            if (ek >= 169) { ek -= 169; pk++; } smf[(int)lut[ek] + pk] = v.y; ek++;
            if (ek >= 169) { ek -= 169; pk++; } smf[(int)lut[ek] + pk] = v.z; ek++;
            if (ek >= 169) { ek -= 169; pk++; } smf[(int)lut[ek] + pk] = v.w;
            // advance by 4*NT = 256 = 169 + 87
            e += 87; p += 1;
            if (e >= 169) { e -= 169; p += 1; }
        }
        for (int idx = limit4 * 4 + tid; idx < limit; idx += NT) {
            const int pp = idx / 169;
            smf[(int)lut[idx - pp * 169] + pp] = Min[(size_t)base * 169 + idx];
        }
    }
    __syncthreads();

    const int gpA = base + 2 * tid;
    if (gpA >= N) return;
    const bool hasB = (gpA + 1) < N;

    // ---- constants ----
    const f2 NEG1 = pk2(-1.0f, -1.0f);
    const f2 ONE2 = pk2( 1.0f,  1.0f);
    const f2 TEN2 = pk2(10.0f, 10.0f);

    // ---- load both problems' T rows 0..2, packed ----
    f2 ta2[3], tb2[3], tc2[3], td2[3];
    {
        const float4* gA = (const float4*)(Tin + (size_t)gpA * 16);
        const float4* gB = (const float4*)(Tin + (size_t)(hasB ? gpA + 1 : gpA) * 16);
        #pragma unroll
        for (int k = 0; k < 3; k++) {
            const float4 fa = gA[k], fb = gB[k];
            ta2[k] = pk2(fa.x, fb.x);
            tb2[k] = pk2(fa.y, fb.y);
            tc2[k] = pk2(fa.z, fb.z);
            td2[k] = pk2(fa.w, fb.w);
        }
    }

    // Q2 persists; after the last iteration its regularized upper 6x6 IS Omega.
    f2 Q2[7][7];

    #pragma unroll 1   // 5 identical GN iterations
    for (int it = 0; it < 5; ++it) {
        // negated copies of rotation entries (used for subtractions in the sweep)
        f2 nta[3], ntb[3], ntc[3];
        #pragma unroll
        for (int k = 0; k < 3; k++) { nta[k] = neg2(ta2[k]); ntb[k] = neg2(tb2[k]); ntc[k] = neg2(tc2[k]); }

        #pragma unroll
        for (int i = 0; i < 7; i++)
            #pragma unroll
            for (int j = i; j < 7; j++) Q2[i][j] = 0ULL;

        // ---- single sweep over M rows (row 9 only feeds unused Q[6][6]) ----
        #pragma unroll
        for (int r = 0; r < 13; r++) {
            if (r == 9) continue;
            f2 m[13];
            #pragma unroll
            for (int c = 0; c < 13; c++)
                m[c] = *(const f2*)&smf[sidx(r, c) * SMS + 2 * tid];

            f2 w[7];
            w[0] = 0ULL; w[1] = 0ULL; w[2] = 0ULL; w[6] = 0ULL;
            #pragma unroll
            for (int k = 0; k < 3; k++) {
                w[0] = fma2(tc2[k], m[3*k+1], w[0]); w[0] = fma2(ntb[k], m[3*k+2], w[0]);
                w[1] = fma2(ta2[k], m[3*k+2], w[1]); w[1] = fma2(ntc[k], m[3*k+0], w[1]);
                w[2] = fma2(tb2[k], m[3*k+0], w[2]); w[2] = fma2(nta[k], m[3*k+1], w[2]);
                w[6] = fma2(ta2[k], m[3*k+0], w[6]);
                w[6] = fma2(tb2[k], m[3*k+1], w[6]);
                w[6] = fma2(tc2[k], m[3*k+2], w[6]);
            }
            w[3] = fma2(ta2[0], m[10], fma2(ta2[1], m[11], mul2(ta2[2], m[12])));
            w[4] = fma2(tb2[0], m[10], fma2(tb2[1], m[11], mul2(tb2[2], m[12])));
            w[5] = fma2(tc2[0], m[10], fma2(tc2[1], m[11], mul2(tc2[2], m[12])));
            w[6] = add2(w[6], m[9]);
            w[6] = fma2(td2[0], m[10], w[6]);
            w[6] = fma2(td2[1], m[11], w[6]);
            w[6] = fma2(td2[2], m[12], w[6]);

            if (r < 9) {
                const int k = r / 3, rr = r - 3 * k;
                if (rr == 0)      { ACC2(1, ntc[k]); ACC2(2, tb2[k]); }
                else if (rr == 1) { ACC2(0, tc2[k]); ACC2(2, nta[k]); }
                else              { ACC2(0, ntb[k]); ACC2(1, ta2[k]); }
            } else {
                const int k = r - 10;
                ACC2(3, ta2[k]); ACC2(4, tb2[k]); ACC2(5, tc2[k]);
            }
        }

        // ---- regularize Q in place (upper 6x6 becomes Omega) ----
        {
            const f2 trs = add2(add2(Q2[3][3], Q2[4][4]), Q2[5][5]);
            float trl, trh; upk2(trs, trl, trh);
            const f2 regT2 = pk2(1e-8f * fmaxf(trl, 1.0f), 1e-8f * fmaxf(trh, 1.0f));
            Q2[0][0] = add2(Q2[0][0], TEN2);
            Q2[1][1] = add2(Q2[1][1], TEN2);
            Q2[2][2] = add2(Q2[2][2], TEN2);
            Q2[3][3] = add2(Q2[3][3], regT2);
            Q2[4][4] = add2(Q2[4][4], regT2);
            Q2[5][5] = add2(Q2[5][5], regT2);
        }
        float mxl, mxh;
        upk2(Q2[0][0], mxl, mxh);
        #pragma unroll
        for (int i = 0; i < 6; i++)
            #pragma unroll
            for (int j = i; j < 6; j++) {
                float a, b; upk2(Q2[i][j], a, b);
                mxl = fmaxf(mxl, a); mxh = fmaxf(mxh, b);
            }
        const f2 reg2 = pk2(1e-5f * (1.0f + mxl), 1e-5f * (1.0f + mxh));

        // ---- packed Cholesky solve (A = Q + reg2 on diag) ; v = -solution ----
        f2 L2[6][6], di2[6];
        #pragma unroll
        for (int j = 0; j < 6; j++) {
            f2 acc = 0ULL;
            #pragma unroll
            for (int k = 0; k < j; k++) acc = fma2(L2[j][k], L2[j][k], acc);
            const f2 s2 = fma2(acc, NEG1, add2(Q2[j][j], reg2));
            float sl, sh; upk2(s2, sl, sh);
            di2[j] = pk2(rsqrtf(sl), rsqrtf(sh));
            #pragma unroll
            for (int i = j + 1; i < 6; i++) {
                f2 a2 = 0ULL;
                #pragma unroll
                for (int k = 0; k < j; k++) a2 = fma2(L2[i][k], L2[j][k], a2);
                L2[i][j] = mul2(fma2(a2, NEG1, Q2[j][i]), di2[j]);
            }
        }
        f2 z2[6];
        #pragma unroll
        for (int i = 0; i < 6; i++) {
            f2 acc = 0ULL;
            #pragma unroll
            for (int k = 0; k < i; k++) acc = fma2(L2[i][k], z2[k], acc);
            z2[i] = mul2(fma2(acc, NEG1, Q2[i][6]), di2[i]);
        }
        f2 v2[6];
        #pragma unroll
        for (int ii = 5; ii >= 0; ii--) {
            f2 acc = 0ULL;
            #pragma unroll
            for (int k = ii + 1; k < 6; k++) acc = fma2(L2[k][ii], v2[k], acc);
            v2[ii] = mul2(fma2(acc, NEG1, z2[ii]), di2[ii]);
        }
        const f2 vx2 = neg2(v2[0]), vy2 = neg2(v2[1]), vz2 = neg2(v2[2]);
        const f2 px2 = neg2(v2[3]), py2 = neg2(v2[4]), pz2 = neg2(v2[5]);

        // ---- closed-form SE(3) exponential (coefs scalar per problem) ----
        const f2 th2_2 = fma2(vx2, vx2, fma2(vy2, vy2, mul2(vz2, vz2)));
        float t2l, t2h; upk2(th2_2, t2l, t2h);
        float sAl, sBl, sCl, sAh, sBh, sCh;
        expm_coefs(t2l, sAl, sBl, sCl);
        expm_coefs(t2h, sAh, sBh, sCh);
        const f2 sA2 = pk2(sAl, sAh), sB2 = pk2(sBl, sBh), sC2 = pk2(sCl, sCh);
        const f2 nsA2 = neg2(sA2), nsB2 = neg2(sB2);

        const f2 k00 = neg2(fma2(vy2, vy2, mul2(vz2, vz2)));
        const f2 k11 = neg2(fma2(vx2, vx2, mul2(vz2, vz2)));
        const f2 k22 = neg2(fma2(vx2, vx2, mul2(vy2, vy2)));
        const f2 kxy = mul2(vx2, vy2), kxz = mul2(vx2, vz2), kyz = mul2(vy2, vz2);

        const f2 R00 = fma2(sB2, k00, ONE2);
        const f2 R01 = fma2(sB2, kxy, mul2(nsA2, vz2));
        const f2 R02 = fma2(sB2, kxz, mul2(sA2,  vy2));
        const f2 R10 = fma2(sB2, kxy, mul2(sA2,  vz2));
        const f2 R11 = fma2(sB2, k11, ONE2);
        const f2 R12 = fma2(sB2, kyz, mul2(nsA2, vx2));
        const f2 R20 = fma2(sB2, kxz, mul2(nsA2, vy2));
        const f2 R21 = fma2(sB2, kyz, mul2(sA2,  vx2));
        const f2 R22 = fma2(sB2, k22, ONE2);

        const f2 V00 = fma2(sC2, k00, ONE2);
        const f2 V01 = fma2(sC2, kxy, mul2(nsB2, vz2));
        const f2 V02 = fma2(sC2, kxz, mul2(sB2,  vy2));
        const f2 V10 = fma2(sC2, kxy, mul2(sB2,  vz2));
        const f2 V11 = fma2(sC2, k11, ONE2);
        const f2 V12 = fma2(sC2, kyz, mul2(nsB2, vx2));
        const f2 V20 = fma2(sC2, kxz, mul2(nsB2, vy2));
        const f2 V21 = fma2(sC2, kyz, mul2(sB2,  vx2));
        const f2 V22 = fma2(sC2, k22, ONE2);

        const f2 et0 = fma2(V00, px2, fma2(V01, py2, mul2(V02, pz2)));
        const f2 et1 = fma2(V10, px2, fma2(V11, py2, mul2(V12, pz2)));
        const f2 et2 = fma2(V20, px2, fma2(V21, py2, mul2(V22, pz2)));

        // ---- T <- T @ expm(hat(v)) (rows 0..2; row 3 unchanged) ----
        #pragma unroll
        for (int k = 0; k < 3; k++) {
            const f2 r0 = ta2[k], r1 = tb2[k], r2 = tc2[k], r3 = td2[k];
            ta2[k] = fma2(r0, R00, fma2(r1, R10, mul2(r2, R20)));
            tb2[k] = fma2(r0, R01, fma2(r1, R11, mul2(r2, R21)));
            tc2[k] = fma2(r0, R02, fma2(r1, R12, mul2(r2, R22)));
            td2[k] = add2(fma2(r0, et0, fma2(r1, et1, mul2(r2, et2))), r3);
        }
    }

    // ---- unpack both problems and store ----
    float Ta[2][3][4];
    #pragma unroll
    for (int k = 0; k < 3; k++) {
        upk2(ta2[k], Ta[0][k][0], Ta[1][k][0]);
        upk2(tb2[k], Ta[0][k][1], Ta[1][k][1]);
        upk2(tc2[k], Ta[0][k][2], Ta[1][k][2]);
        upk2(td2[k], Ta[0][k][3], Ta[1][k][3]);
    }
    float Qs[2][21];
    #pragma unroll
    for (int i = 0; i < 6; i++)
        #pragma unroll
        for (int j = i; j < 6; j++)
            upk2(Q2[i][j], Qs[0][tidx6(i, j)], Qs[1][tidx6(i, j)]);

    #pragma unroll
    for (int P = 0; P < 2; P++) {
        if (P == 1 && !hasB) break;
        const int gp = gpA + P;

        float4* oT = (float4*)(outT + (size_t)gp * 16);
        #pragma unroll
        for (int k = 0; k < 3; k++)
            oT[k] = make_float4(Ta[P][k][0], Ta[P][k][1], Ta[P][k][2], Ta[P][k][3]);
        // row 3 of T unchanged by boxplus (expm row3 = [0,0,0,1])
        oT[3] = ((const float4*)(Tin + (size_t)gp * 16))[3];

        const float tzf = Ta[P][2][3];
        const float sc  = 1.0f / (tzf * tzf + 1e-8f);

        float Of[36];
        #pragma unroll
        for (int i = 0; i < 6; i++)
            #pragma unroll
            for (int j = 0; j < 6; j++)
                Of[i*6 + j] = ((i <= j) ? Qs[P][tidx6(i, j)] : Qs[P][tidx6(j, i)]) * sc;

        float4* oO = (float4*)(outOm + (size_t)gp * 36);
        #pragma unroll
        for (int v4 = 0; v4 < 9; v4++)
            oO[v4] = make_float4(Of[v4*4+0], Of[v4*4+1], Of[v4*4+2], Of[v4*4+3]);
    }
}

extern "C" void kernel_launch(void* const* d_in, const int* in_sizes, int n_in,
                              void* d_out, int out_size)
{
    const float* Min = (const float*)d_in[0];   // MTMs [B,C,13,13] fp32
    const float* Tin = (const float*)d_in[1];   // Ts   [B,C,4,4]   fp32
    const int N = in_sizes[0] / 169;

    float* out   = (float*)d_out;
    float* outT  = out;                          // [N,4,4]
    float* outOm = out + (size_t)N * 16;         // [N,6,6]

    const int blocks = (N + NPB - 1) / NPB;
    mtm_refine_kernel<<<blocks, NT>>>(Min, Tin, outT, outOm, N);
}

// round 14
// speedup vs baseline: 1.1420x; 1.1420x over previous
#include <cuda_runtime.h>
#include <cstdint>

#define NT  64
#define NPB 64
#define SMS 65   // (s*65 + p) % 32 = (s + p) % 32

// packed symmetric index for 13x13 (upper triangle), compile-time after unroll
__device__ __forceinline__ int sidx(int r, int c) {
    int lo = r < c ? r : c;
    int hi = r < c ? c : r;
    return lo * 13 - (lo * (lo - 1)) / 2 + (hi - lo);
}

// accumulate P[r,I]*w[j] into upper-tri Q (I is a literal)
#define ACC(I, P) do { const float p_ = (P); _Pragma("unroll") \
    for (int j = (I); j < 7; j++) Q[(I)][j] += p_ * w[j]; } while (0)

__global__ void __launch_bounds__(NT, 6)
mtm_refine_kernel(const float* __restrict__ Min, const float* __restrict__ Tin,
                  float* __restrict__ outT, float* __restrict__ outOm, int N)
{
    __shared__ float sm[91 * SMS];            // 23,660 B (fill staging)
    __shared__ unsigned short lut[169];       // element -> packed slot * SMS

    const int tid  = threadIdx.x;
    const int base = blockIdx.x * NPB;

    // ---- element->packed-slot LUT ----
    for (int e = tid; e < 169; e += NT) {
        const int r = e / 13, c = e - (e / 13) * 13;
        const int lo = r < c ? r : c;
        const int hi = r < c ? c : r;
        lut[e] = (unsigned short)((lo * 13 - ((lo * (lo - 1)) >> 1) + (hi - lo)) * SMS);
    }
    __syncthreads();

    // ---- R5-proven vectorized cooperative fill (float4 LDG + LUT STS) ----
    {
        int np = N - base; if (np > NPB) np = NPB;
        const int limit  = np * 169;
        const int limit4 = limit >> 2;
        const float4* g4 = (const float4*)(Min + (size_t)base * 169);

        int p = 0, e = 4 * tid;
        if (e >= 169) { e -= 169; p++; }     // 4*tid <= 252 < 338
        for (int i4 = tid; i4 < limit4; i4 += NT) {
            const float4 v = g4[i4];
            int ek = e, pk = p;
            if (ek >= 169) { ek -= 169; pk++; } sm[(int)lut[ek] + pk] = v.x; ek++;
            if (ek >= 169) { ek -= 169; pk++; } sm[(int)lut[ek] + pk] = v.y; ek++;
            if (ek >= 169) { ek -= 169; pk++; } sm[(int)lut[ek] + pk] = v.z; ek++;
            if (ek >= 169) { ek -= 169; pk++; } sm[(int)lut[ek] + pk] = v.w;
            // advance by 4*NT = 256 = 169 + 87
            e += 87; p += 1;
            if (e >= 169) { e -= 169; p += 1; }
        }
        for (int idx = limit4 * 4 + tid; idx < limit; idx += NT) {
            const int pp = idx / 169;
            sm[(int)lut[idx - pp * 169] + pp] = Min[(size_t)base * 169 + idx];
        }
    }
    __syncthreads();

    const int gp = base + tid;
    if (gp >= N) return;

    // ---- copy this thread's packed M into registers (conflict-free LDS burst) ----
    float M[91];
    #pragma unroll
    for (int s = 0; s < 91; s++)
        M[s] = sm[s * SMS + tid];

    // ---- load T rows 0..2: (ta,tb,tc,td)[k] ----
    float ta[3], tb[3], tc[3], td[3];
    {
        const float4* gT = (const float4*)(Tin + (size_t)gp * 16);
        #pragma unroll
        for (int k = 0; k < 3; k++) {
            float4 f = gT[k];
            ta[k] = f.x; tb[k] = f.y; tc[k] = f.z; td[k] = f.w;
        }
    }

    // Q persists across iterations; after the last iteration its upper 6x6
    // (diag-regularized in place) IS Omega.
    float Q[7][7];

    #pragma unroll 1   // 5 identical GN iterations
    for (int it = 0; it < 5; ++it) {
        #pragma unroll
        for (int i = 0; i < 7; i++)
            #pragma unroll
            for (int j = i; j < 7; j++) Q[i][j] = 0.0f;

        // ---- single sweep over M rows, all operands in registers ----
        #pragma unroll
        for (int r = 0; r < 13; r++) {
            if (r == 9) continue;    // row 9 feeds only unused Q[6][6]
            float m[13];
            #pragma unroll
            for (int c = 0; c < 13; c++) m[c] = M[sidx(r, c)];

            float w[7];
            w[0] = 0.f; w[1] = 0.f; w[2] = 0.f; w[6] = 0.f;
            #pragma unroll
            for (int k = 0; k < 3; k++) {
                w[0] += tc[k]*m[3*k+1] - tb[k]*m[3*k+2];
                w[1] += ta[k]*m[3*k+2] - tc[k]*m[3*k+0];
                w[2] += tb[k]*m[3*k+0] - ta[k]*m[3*k+1];
                w[6] += ta[k]*m[3*k+0] + tb[k]*m[3*k+1] + tc[k]*m[3*k+2];
            }
            w[3] = ta[0]*m[10] + ta[1]*m[11] + ta[2]*m[12];
            w[4] = tb[0]*m[10] + tb[1]*m[11] + tb[2]*m[12];
            w[5] = tc[0]*m[10] + tc[1]*m[11] + tc[2]*m[12];
            w[6] += m[9] + td[0]*m[10] + td[1]*m[11] + td[2]*m[12];

            if (r < 9) {
                const int k = r / 3, rr = r - 3 * k;
                if (rr == 0)      { ACC(1, -tc[k]); ACC(2,  tb[k]); }
                else if (rr == 1) { ACC(0,  tc[k]); ACC(2, -ta[k]); }
                else              { ACC(0, -tb[k]); ACC(1,  ta[k]); }
            } else {
                const int k = r - 10;
                ACC(3, ta[k]); ACC(4, tb[k]); ACC(5, tc[k]);
            }
        }

        // ---- regularize Q in place: upper 6x6 becomes Omega ----
        const float regT = 1e-8f * fmaxf(Q[3][3] + Q[4][4] + Q[5][5], 1.0f);
        Q[0][0] += 10.0f; Q[1][1] += 10.0f; Q[2][2] += 10.0f;
        Q[3][3] += regT;  Q[4][4] += regT;  Q[5][5] += regT;

        float mx = Q[0][0];
        #pragma unroll
        for (int i = 0; i < 6; i++)
            #pragma unroll
            for (int j = i; j < 6; j++) mx = fmaxf(mx, Q[i][j]);
        const float reg = 1e-5f * (1.0f + mx);

        float A[6][6];   // upper-tri only
        #pragma unroll
        for (int i = 0; i < 6; i++)
            #pragma unroll
            for (int j = i; j < 6; j++)
                A[i][j] = Q[i][j] + ((i == j) ? reg : 0.0f);

        // ---- Cholesky solve A v' = q ; v = -v' ----
        float L[6][6], di[6];
        #pragma unroll
        for (int j = 0; j < 6; j++) {
            float s = A[j][j];
            #pragma unroll
            for (int k = 0; k < j; k++) s -= L[j][k] * L[j][k];
            di[j] = rsqrtf(s);
            #pragma unroll
            for (int i = j + 1; i < 6; i++) {
                float t = A[j][i];
                #pragma unroll
                for (int k = 0; k < j; k++) t -= L[i][k] * L[j][k];
                L[i][j] = t * di[j];
            }
        }
        float z[6];
        #pragma unroll
        for (int i = 0; i < 6; i++) {
            float s = Q[i][6];              // q[i]
            #pragma unroll
            for (int k = 0; k < i; k++) s -= L[i][k] * z[k];
            z[i] = s * di[i];
        }
        float w6v[6];
        #pragma unroll
        for (int ii = 5; ii >= 0; ii--) {
            float s = z[ii];
            #pragma unroll
            for (int k = ii + 1; k < 6; k++) s -= L[k][ii] * w6v[k];
            w6v[ii] = s * di[ii];
        }

        const float vx = -w6v[0], vy = -w6v[1], vz = -w6v[2];
        const float px = -w6v[3], py = -w6v[4], pz = -w6v[5];

        // ---- closed-form SE(3) exponential ----
        const float th2 = vx*vx + vy*vy + vz*vz;
        float sA, sB, sC;
        if (th2 > 1e-2f) {
            const float th = sqrtf(th2);
            float sn, cn;
            __sincosf(th, &sn, &cn);
            sA = sn / th;
            sB = (1.0f - cn) / th2;
            sC = (1.0f - sA) / th2;
        } else {
            sA = 1.0f - th2 * (1.0f/6.0f)  + th2*th2 * (1.0f/120.0f);
            sB = 0.5f - th2 * (1.0f/24.0f) + th2*th2 * (1.0f/720.0f);
            sC = (1.0f/6.0f) - th2 * (1.0f/120.0f) + th2*th2 * (1.0f/5040.0f);
        }
        const float k00 = -(vy*vy + vz*vz), k11 = -(vx*vx + vz*vz), k22 = -(vx*vx + vy*vy);
        const float kxy = vx*vy, kxz = vx*vz, kyz = vy*vz;

        const float R00 = 1.0f + sB*k00, R01 = -sA*vz + sB*kxy, R02 =  sA*vy + sB*kxz;
        const float R10 =  sA*vz + sB*kxy, R11 = 1.0f + sB*k11, R12 = -sA*vx + sB*kyz;
        const float R20 = -sA*vy + sB*kxz, R21 =  sA*vx + sB*kyz, R22 = 1.0f + sB*k22;

        const float V00 = 1.0f + sC*k00, V01 = -sB*vz + sC*kxy, V02 =  sB*vy + sC*kxz;
        const float V10 =  sB*vz + sC*kxy, V11 = 1.0f + sC*k11, V12 = -sB*vx + sC*kyz;
        const float V20 = -sB*vy + sC*kxz, V21 =  sB*vx + sC*kyz, V22 = 1.0f + sC*k22;

        const float et0 = V00*px + V01*py + V02*pz;
        const float et1 = V10*px + V11*py + V12*pz;
        const float et2 = V20*px + V21*py + V22*pz;

        // ---- T <- T @ expm(hat(v)) (rows 0..2; row 3 unchanged) ----
        #pragma unroll
        for (int k = 0; k < 3; k++) {
            const float r0 = ta[k], r1 = tb[k], r2 = tc[k], r3 = td[k];
            ta[k] = r0*R00 + r1*R10 + r2*R20;
            tb[k] = r0*R01 + r1*R11 + r2*R21;
            tc[k] = r0*R02 + r1*R12 + r2*R22;
            td[k] = r0*et0 + r1*et1 + r2*et2 + r3;
        }
    }

    // ---- outputs (float32): T, then Omega / (t_z^2 + 1e-8) ----
    const float tzf = td[2];
    const float sc  = 1.0f / (tzf * tzf + 1e-8f);

    float4* oT = (float4*)(outT + (size_t)gp * 16);
    #pragma unroll
    for (int k = 0; k < 3; k++)
        oT[k] = make_float4(ta[k], tb[k], tc[k], td[k]);
    // row 3 of T unchanged by boxplus (expm row3 = [0,0,0,1])
    oT[3] = ((const float4*)(Tin + (size_t)gp * 16))[3];

    // Omega is the last iteration's regularized Q (upper 6x6)
    float Of[36];
    #pragma unroll
    for (int i = 0; i < 6; i++)
        #pragma unroll
        for (int j = 0; j < 6; j++)
            Of[i*6 + j] = ((i <= j) ? Q[i][j] : Q[j][i]) * sc;

    float4* oO = (float4*)(outOm + (size_t)gp * 36);
    #pragma unroll
    for (int v4 = 0; v4 < 9; v4++)
        oO[v4] = make_float4(Of[v4*4+0], Of[v4*4+1], Of[v4*4+2], Of[v4*4+3]);
}

extern "C" void kernel_launch(void* const* d_in, const int* in_sizes, int n_in,
                              void* d_out, int out_size)
{
    const float* Min = (const float*)d_in[0];   // MTMs [B,C,13,13] fp32
    const float* Tin = (const float*)d_in[1];   // Ts   [B,C,4,4]   fp32
    const int N = in_sizes[0] / 169;

    float* out   = (float*)d_out;
    float* outT  = out;                          // [N,4,4]
    float* outOm = out + (size_t)N * 16;         // [N,6,6]

    const int blocks = (N + NPB - 1) / NPB;
    mtm_refine_kernel<<<blocks, NT>>>(Min, Tin, outT, outOm, N);
}

// round 15
// speedup vs baseline: 1.5107x; 1.3229x over previous
#include <cuda_runtime.h>
#include <cstdint>

#define NT  64
#define NPB 64
#define SMS 65   // (s*65 + p) % 32 = (s + p) % 32

// packed symmetric index for 13x13 (upper triangle), compile-time after unroll
__device__ __forceinline__ int sidx(int r, int c) {
    int lo = r < c ? r : c;
    int hi = r < c ? c : r;
    return lo * 13 - (lo * (lo - 1)) / 2 + (hi - lo);
}

#define MM(r, c) sm[sidx((r), (c)) * SMS + tid]

// accumulate P[r,I]*w[j] into upper-tri Q (I is a literal)
#define ACC(I, P) do { const float p_ = (P); _Pragma("unroll") \
    for (int j = (I); j < 7; j++) Q[(I)][j] += p_ * w[j]; } while (0)

// specialized T0 row: Q[I][j] += SGN * w_row(R)[j]; unused w entries are DCE'd
#define SPECROW(R, I, SGNF) do { \
    float w_[7]; \
    w_[0] = MM(R,7)  - MM(R,5); \
    w_[1] = MM(R,2)  - MM(R,6); \
    w_[2] = MM(R,3)  - MM(R,1); \
    w_[3] = MM(R,10); \
    w_[4] = MM(R,11); \
    w_[5] = MM(R,12); \
    w_[6] = MM(R,0) + MM(R,4) + MM(R,8) + MM(R,9) + MM(R,12); \
    _Pragma("unroll") \
    for (int j = (I); j < 7; j++) Q[(I)][j] += (SGNF) * w_[j]; \
} while (0)

__global__ void __launch_bounds__(NT, 9)
mtm_refine_kernel(const float* __restrict__ Min, const float* __restrict__ Tin,
                  float* __restrict__ outT, float* __restrict__ outOm, int N)
{
    __shared__ float sm[91 * SMS];            // 23,660 B
    __shared__ unsigned short lut[169];       // element -> packed slot * SMS

    const int tid  = threadIdx.x;
    const int base = blockIdx.x * NPB;

    // ---- element->packed-slot LUT ----
    for (int e = tid; e < 169; e += NT) {
        const int r = e / 13, c = e - (e / 13) * 13;
        const int lo = r < c ? r : c;
        const int hi = r < c ? c : r;
        lut[e] = (unsigned short)((lo * 13 - ((lo * (lo - 1)) >> 1) + (hi - lo)) * SMS);
    }
    __syncthreads();

    // ---- R5-proven vectorized cooperative fill (float4 LDG + LUT STS) ----
    {
        int np = N - base; if (np > NPB) np = NPB;
        const int limit  = np * 169;
        const int limit4 = limit >> 2;
        const float4* g4 = (const float4*)(Min + (size_t)base * 169);

        int p = 0, e = 4 * tid;
        if (e >= 169) { e -= 169; p++; }     // 4*tid <= 252 < 338
        for (int i4 = tid; i4 < limit4; i4 += NT) {
            const float4 v = g4[i4];
            int ek = e, pk = p;
            if (ek >= 169) { ek -= 169; pk++; } sm[(int)lut[ek] + pk] = v.x; ek++;
            if (ek >= 169) { ek -= 169; pk++; } sm[(int)lut[ek] + pk] = v.y; ek++;
            if (ek >= 169) { ek -= 169; pk++; } sm[(int)lut[ek] + pk] = v.z; ek++;
            if (ek >= 169) { ek -= 169; pk++; } sm[(int)lut[ek] + pk] = v.w;
            // advance by 4*NT = 256 = 169 + 87
            e += 87; p += 1;
            if (e >= 169) { e -= 169; p += 1; }
        }
        for (int idx = limit4 * 4 + tid; idx < limit; idx += NT) {
            const int pp = idx / 169;
            sm[(int)lut[idx - pp * 169] + pp] = Min[(size_t)base * 169 + idx];
        }
    }
    __syncthreads();

    const int gp = base + tid;
    if (gp >= N) return;

    // ---- load T rows 0..2: (ta,tb,tc,td)[k] ----
    float ta[3], tb[3], tc[3], td[3];
    {
        const float4* gT = (const float4*)(Tin + (size_t)gp * 16);
        #pragma unroll
        for (int k = 0; k < 3; k++) {
            float4 f = gT[k];
            ta[k] = f.x; tb[k] = f.y; tc[k] = f.z; td[k] = f.w;
        }
    }

    // T0 = identity pose with t_z = 1 (exact fp32). All dataset problems start here;
    // the guard keeps the kernel correct for arbitrary T.
    const bool isT0 =
        ta[0] == 1.0f && tb[0] == 0.0f && tc[0] == 0.0f && td[0] == 0.0f &&
        ta[1] == 0.0f && tb[1] == 1.0f && tc[1] == 0.0f && td[1] == 0.0f &&
        ta[2] == 0.0f && tb[2] == 0.0f && tc[2] == 1.0f && td[2] == 1.0f;

    float OmU[6][6];   // upper-tri Omega of last iteration

    #pragma unroll 1   // 5 identical GN iterations; bound I$ footprint
    for (int it = 0; it < 5; ++it) {
        float Q[7][7];
        #pragma unroll
        for (int i = 0; i < 7; i++)
            #pragma unroll
            for (int j = i; j < 7; j++) Q[i][j] = 0.0f;

        if (it == 0 && isT0) {
            // ---- specialized first sweep at T0: P entries are 0/±1, rows 0,4,8,9 drop ----
            SPECROW(1, 2, -1.0f);
            SPECROW(2, 1,  1.0f);
            SPECROW(3, 2,  1.0f);
            SPECROW(5, 0, -1.0f);
            SPECROW(6, 1, -1.0f);
            SPECROW(7, 0,  1.0f);
            SPECROW(10, 3, 1.0f);
            SPECROW(11, 4, 1.0f);
            SPECROW(12, 5, 1.0f);
        } else {
            // ---- generic single sweep over M rows (row 9 only feeds unused Q[6][6]) ----
            #pragma unroll
            for (int r = 0; r < 13; r++) {
                if (r == 9) continue;
                float m[13];
                #pragma unroll
                for (int c = 0; c < 13; c++) m[c] = MM(r, c);

                float w[7];
                w[0] = 0.f; w[1] = 0.f; w[2] = 0.f; w[6] = 0.f;
                #pragma unroll
                for (int k = 0; k < 3; k++) {
                    w[0] += tc[k]*m[3*k+1] - tb[k]*m[3*k+2];
                    w[1] += ta[k]*m[3*k+2] - tc[k]*m[3*k+0];
                    w[2] += tb[k]*m[3*k+0] - ta[k]*m[3*k+1];
                    w[6] += ta[k]*m[3*k+0] + tb[k]*m[3*k+1] + tc[k]*m[3*k+2];
                }
                w[3] = ta[0]*m[10] + ta[1]*m[11] + ta[2]*m[12];
                w[4] = tb[0]*m[10] + tb[1]*m[11] + tb[2]*m[12];
                w[5] = tc[0]*m[10] + tc[1]*m[11] + tc[2]*m[12];
                w[6] += m[9] + td[0]*m[10] + td[1]*m[11] + td[2]*m[12];

                if (r < 9) {
                    const int k = r / 3, rr = r - 3 * k;
                    if (rr == 0)      { ACC(1, -tc[k]); ACC(2,  tb[k]); }
                    else if (rr == 1) { ACC(0,  tc[k]); ACC(2, -ta[k]); }
                    else              { ACC(0, -tb[k]); ACC(1,  ta[k]); }
                } else {
                    const int k = r - 10;
                    ACC(3, ta[k]); ACC(4, tb[k]); ACC(5, tc[k]);
                }
            }
        }

        // ---- regularization (matches reference) ----
        const float regT = 1e-8f * fmaxf(Q[3][3] + Q[4][4] + Q[5][5], 1.0f);
        #pragma unroll
        for (int i = 0; i < 6; i++) {
            const float dd = (i < 3) ? 10.0f : regT;
            #pragma unroll
            for (int j = i; j < 6; j++)
                OmU[i][j] = Q[i][j] + ((i == j) ? dd : 0.0f);
        }
        float mx = OmU[0][0];
        #pragma unroll
        for (int i = 0; i < 6; i++)
            #pragma unroll
            for (int j = i; j < 6; j++) mx = fmaxf(mx, OmU[i][j]);
        const float reg = 1e-5f * (1.0f + mx);

        float A[6][6];   // upper-tri only
        #pragma unroll
        for (int i = 0; i < 6; i++)
            #pragma unroll
            for (int j = i; j < 6; j++)
                A[i][j] = OmU[i][j] + ((i == j) ? reg : 0.0f);

        // ---- Cholesky solve A v' = q ; v = -v' ----
        float L[6][6], di[6];
        #pragma unroll
        for (int j = 0; j < 6; j++) {
            float s = A[j][j];
            #pragma unroll
            for (int k = 0; k < j; k++) s -= L[j][k] * L[j][k];
            di[j] = rsqrtf(s);
            #pragma unroll
            for (int i = j + 1; i < 6; i++) {
                float t = A[j][i];
                #pragma unroll
                for (int k = 0; k < j; k++) t -= L[i][k] * L[j][k];
                L[i][j] = t * di[j];
            }
        }
        float z[6];
        #pragma unroll
        for (int i = 0; i < 6; i++) {
            float s = Q[i][6];              // q[i]
            #pragma unroll
            for (int k = 0; k < i; k++) s -= L[i][k] * z[k];
            z[i] = s * di[i];
        }
        float w6v[6];
        #pragma unroll
        for (int ii = 5; ii >= 0; ii--) {
            float s = z[ii];
            #pragma unroll
            for (int k = ii + 1; k < 6; k++) s -= L[k][ii] * w6v[k];
            w6v[ii] = s * di[ii];
        }

        const float vx = -w6v[0], vy = -w6v[1], vz = -w6v[2];
        const float px = -w6v[3], py = -w6v[4], pz = -w6v[5];

        // ---- closed-form SE(3) exponential ----
        const float th2 = vx*vx + vy*vy + vz*vz;
        float sA, sB, sC;
        if (th2 > 1e-2f) {
            const float th = sqrtf(th2);
            float sn, cn;
            __sincosf(th, &sn, &cn);
            sA = sn / th;
            sB = (1.0f - cn) / th2;
            sC = (1.0f - sA) / th2;
        } else {
            sA = 1.0f - th2 * (1.0f/6.0f)  + th2*th2 * (1.0f/120.0f);
            sB = 0.5f - th2 * (1.0f/24.0f) + th2*th2 * (1.0f/720.0f);
            sC = (1.0f/6.0f) - th2 * (1.0f/120.0f) + th2*th2 * (1.0f/5040.0f);
        }
        const float k00 = -(vy*vy + vz*vz), k11 = -(vx*vx + vz*vz), k22 = -(vx*vx + vy*vy);
        const float kxy = vx*vy, kxz = vx*vz, kyz = vy*vz;

        const float R00 = 1.0f + sB*k00, R01 = -sA*vz + sB*kxy, R02 =  sA*vy + sB*kxz;
        const float R10 =  sA*vz + sB*kxy, R11 = 1.0f + sB*k11, R12 = -sA*vx + sB*kyz;
        const float R20 = -sA*vy + sB*kxz, R21 =  sA*vx + sB*kyz, R22 = 1.0f + sB*k22;

        const float V00 = 1.0f + sC*k00, V01 = -sB*vz + sC*kxy, V02 =  sB*vy + sC*kxz;
        const float V10 =  sB*vz + sC*kxy, V11 = 1.0f + sC*k11, V12 = -sB*vx + sC*kyz;
        const float V20 = -sB*vy + sC*kxz, V21 =  sB*vx + sC*kyz, V22 = 1.0f + sC*k22;

        const float et0 = V00*px + V01*py + V02*pz;
        const float et1 = V10*px + V11*py + V12*pz;
        const float et2 = V20*px + V21*py + V22*pz;

        // ---- T <- T @ expm(hat(v)) (rows 0..2; row 3 unchanged) ----
        #pragma unroll
        for (int k = 0; k < 3; k++) {
            const float r0 = ta[k], r1 = tb[k], r2 = tc[k], r3 = td[k];
            ta[k] = r0*R00 + r1*R10 + r2*R20;
            tb[k] = r0*R01 + r1*R11 + r2*R21;
            tc[k] = r0*R02 + r1*R12 + r2*R22;
            td[k] = r0*et0 + r1*et1 + r2*et2 + r3;
        }
    }

    // ---- outputs (float32): T, then Omega / (t_z^2 + 1e-8) ----
    const float tzf = td[2];
    const float sc  = 1.0f / (tzf * tzf + 1e-8f);

    float4* oT = (float4*)(outT + (size_t)gp * 16);
    #pragma unroll
    for (int k = 0; k < 3; k++)
        oT[k] = make_float4(ta[k], tb[k], tc[k], td[k]);
    // last row of T unchanged by boxplus (expm row3 = [0,0,0,1])
    oT[3] = ((const float4*)(Tin + (size_t)gp * 16))[3];

    float Of[36];
    #pragma unroll
    for (int i = 0; i < 6; i++)
        #pragma unroll
        for (int j = 0; j < 6; j++)
            Of[i*6 + j] = ((i <= j) ? OmU[i][j] : OmU[j][i]) * sc;

    float4* oO = (float4*)(outOm + (size_t)gp * 36);
    #pragma unroll
    for (int v4 = 0; v4 < 9; v4++)
        oO[v4] = make_float4(Of[v4*4+0], Of[v4*4+1], Of[v4*4+2], Of[v4*4+3]);
}

extern "C" void kernel_launch(void* const* d_in, const int* in_sizes, int n_in,
                              void* d_out, int out_size)
{
    const float* Min = (const float*)d_in[0];   // MTMs [B,C,13,13] fp32
    const float* Tin = (const float*)d_in[1];   // Ts   [B,C,4,4]   fp32
    const int N = in_sizes[0] / 169;

    float* out   = (float*)d_out;
    float* outT  = out;                          // [N,4,4]
    float* outOm = out + (size_t)N * 16;         // [N,6,6]

    const int blocks = (N + NPB - 1) / NPB;
    mtm_refine_kernel<<<blocks, NT>>>(Min, Tin, outT, outOm, N);
}